// round 3
// baseline (speedup 1.0000x reference)
#include <cuda_runtime.h>
#include <cstdint>

// Problem constants (shapes fixed by setup_inputs)
constexpr int   B = 8, F = 16, K = 24;
constexpr int   L = 384 * 384;          // 147456 pixels per (b, plane)
constexpr float EPSV       = 1e-8f;
constexpr float DELTA_VAR  = 0.5f;
constexpr float DELTA_DIST = 1.5f;
constexpr float GAMMA      = 0.001f;

// Scratch (device globals: no allocation allowed)
__device__ float g_sums[B * F * K];
__device__ float g_tsum[B * K];
__device__ float g_means[B * F * K];
__device__ float g_m2[B * K];
__device__ float g_cvar[B * K];
__device__ float g_distreg[2];          // [0]=dist_term (already /B), [1]=reg sum (already /B, pre-GAMMA)
__device__ unsigned char g_labels[B * L];

// ---------------------------------------------------------------------------
// K0: zero the accumulators (graph replays must be deterministic)
// ---------------------------------------------------------------------------
__global__ void k_init() {
    int i = blockIdx.x * blockDim.x + threadIdx.x;
    if (i < B * F * K) g_sums[i] = 0.f;
    if (i < B * K) { g_tsum[i] = 0.f; g_cvar[i] = 0.f; }
    if (i < 2) g_distreg[i] = 0.f;
}

// ---------------------------------------------------------------------------
// K1: sums[b,f,c] = sum_l x[b,f,l]*t[b,c,l];  t_sum[b,c]; per-pixel labels.
// Tiled: 128 pixels/tile, 8 tiles/block, grid (144, 8).
// 256 threads = 16 groups of 16; thread (g,i) accumulates f=i over 24 clusters
// for group g's pixels (broadcast shared reads of t rows).
// ---------------------------------------------------------------------------
constexpr int TP  = 128;                 // pixels per tile
constexpr int TPB = 8;                   // tiles per block
constexpr int NCHUNK = L / (TP * TPB);   // 144
constexpr int XST = 132;                 // padded row stride (floats)

__global__ __launch_bounds__(256, 4) void k_sums(const float* __restrict__ x,
                                                 const float* __restrict__ t) {
    __shared__ float pool[6144];         // union: load tiles / reduction buffer
    __shared__ unsigned char labels_s[TP];
    float* Xs = pool;                    // [16][132]
    float* Ts = pool + F * XST;          // [24][132]

    const int tid  = threadIdx.x;
    const int w    = tid >> 5;           // warp 0..7
    const int lane = tid & 31;
    const int b    = blockIdx.y;
    const int g    = tid >> 4;           // group 0..15
    const int fi   = tid & 15;           // feature index for compute phase
    const float* xb = x + (size_t)(b * F) * L;
    const float* tb = t + (size_t)(b * K) * L;

    float acc[K];
#pragma unroll
    for (int c = 0; c < K; c++) acc[c] = 0.f;
    float ts0 = 0.f, ts1 = 0.f, ts2 = 0.f;

    const int l0b = blockIdx.x * (TP * TPB);

    // x-load geometry: warp w owns feature rows 2w and 2w+1; within the warp,
    // lanes 0-15 load row 2w, lanes 16-31 load row 2w+1, each lane 8 floats
    // (one 256-bit ld with evict_last hint).
    const int xf_row = 2 * w + (lane >> 4);
    const int xoff   = (lane & 15) * 8;

    for (int tile = 0; tile < TPB; ++tile) {
        const int l0 = l0b + tile * TP;

        // ---- load x (256-bit, L2 evict_last) ----
        {
            const float* p = xb + (size_t)xf_row * L + l0 + xoff;
            uint32_t r0, r1, r2, r3, r4, r5, r6, r7;
            asm volatile(
                "ld.global.L2::evict_last.v8.b32 {%0,%1,%2,%3,%4,%5,%6,%7}, [%8];"
                : "=r"(r0), "=r"(r1), "=r"(r2), "=r"(r3),
                  "=r"(r4), "=r"(r5), "=r"(r6), "=r"(r7)
                : "l"(p));
            uint4* s = (uint4*)(Xs + xf_row * XST + xoff);
            s[0] = make_uint4(r0, r1, r2, r3);
            s[1] = make_uint4(r4, r5, r6, r7);
        }
        // ---- load t: warp w handles cluster rows 3w..3w+2 (streaming) ----
#pragma unroll
        for (int r = 0; r < 3; r++) {
            const int c = 3 * w + r;
            float4 v = __ldcs((const float4*)(tb + (size_t)c * L + l0 + lane * 4));
            const float s = (v.x + v.y) + (v.z + v.w);
            if (r == 0) ts0 += s; else if (r == 1) ts1 += s; else ts2 += s;
            *(float4*)(Ts + c * XST + lane * 4) = v;
            const int p0 = lane * 4;     // t is exactly one-hot: record label
            if (v.x != 0.f) labels_s[p0 + 0] = (unsigned char)c;
            if (v.y != 0.f) labels_s[p0 + 1] = (unsigned char)c;
            if (v.z != 0.f) labels_s[p0 + 2] = (unsigned char)c;
            if (v.w != 0.f) labels_s[p0 + 3] = (unsigned char)c;
        }
        __syncthreads();

        // labels -> gmem (coalesced 32B x 4)
        if (tid < TP / 4) {
            uint32_t lv = *(const uint32_t*)&labels_s[tid * 4];
            *(uint32_t*)(g_labels + (size_t)b * L + l0 + tid * 4) = lv;
        }

        // ---- compute: group g covers pixel quads 2g, 2g+1 ----
#pragma unroll
        for (int qi = 0; qi < 2; ++qi) {
            const int q = g * 2 + qi;
            const float4 xf = *(const float4*)(Xs + fi * XST + q * 4);
#pragma unroll
            for (int c = 0; c < K; c++) {
                const float4 tv = *(const float4*)(Ts + c * XST + q * 4); // broadcast
                acc[c] += xf.x * tv.x + xf.y * tv.y + xf.z * tv.z + xf.w * tv.w;
            }
        }
        __syncthreads();
    }

    // ---- block reduction of acc across the 16 groups ----
#pragma unroll
    for (int c = 0; c < K; c++) pool[tid * K + c] = acc[c];
    __syncthreads();
    // F*K = 384 > 256 threads: strided loop (the round-2 bug was `if (tid<F*K)`)
    for (int i = tid; i < F * K; i += 256) {
        const int f = i / K, c = i % K;
        float s = 0.f;
#pragma unroll
        for (int gg = 0; gg < 16; gg++) s += pool[(gg * 16 + f) * K + c];
        atomicAdd(&g_sums[(b * F + f) * K + c], s);
    }
    // ---- t_sum: warp reduce loader partials ----
#pragma unroll
    for (int off = 16; off; off >>= 1) {
        ts0 += __shfl_down_sync(0xffffffffu, ts0, off);
        ts1 += __shfl_down_sync(0xffffffffu, ts1, off);
        ts2 += __shfl_down_sync(0xffffffffu, ts2, off);
    }
    if (lane == 0) {
        atomicAdd(&g_tsum[b * K + 3 * w + 0], ts0);
        atomicAdd(&g_tsum[b * K + 3 * w + 1], ts1);
        atomicAdd(&g_tsum[b * K + 3 * w + 2], ts2);
    }
}

// ---------------------------------------------------------------------------
// K2: means, m2, pairwise-distance hinge term, regularization term.
// One block per b, 576 threads (= 24*24 pairs).
// ---------------------------------------------------------------------------
__global__ void k_means(const int* __restrict__ n_clusters) {
    __shared__ float ms[F * K];
    __shared__ float m2s[K];
    __shared__ float red[32];

    const int b   = blockIdx.x;
    const int tid = threadIdx.x;
    const int nc  = n_clusters[b];
    const float ncf = (float)nc;

    if (tid < F * K) {
        const int c = tid % K;
        float m = g_sums[b * F * K + tid] / (g_tsum[b * K + c] + EPSV);
        m = (c < nc) ? m : 0.f;
        ms[tid] = m;
        g_means[b * F * K + tid] = m;
    }
    __syncthreads();
    if (tid < K) {
        float m2 = 0.f;
#pragma unroll
        for (int f = 0; f < F; f++) { const float v = ms[f * K + tid]; m2 += v * v; }
        m2s[tid] = m2;
        g_m2[b * K + tid] = m2;
    }
    __syncthreads();

    // reg term contribution (per valid cluster)
    float regp = 0.f;
    if (tid < K && tid < nc) {
        const float m2 = m2s[tid];
        regp = (m2 > 0.f) ? sqrtf(m2) : 0.f;
    }
    // pairwise hinge
    float hs = 0.f;
    {
        const int cc = tid / K, dd = tid % K;
        if (cc != dd && cc < nc && dd < nc) {
            float mm = 0.f;
#pragma unroll
            for (int f = 0; f < F; f++) mm += ms[f * K + cc] * ms[f * K + dd];
            float pd2 = fmaxf(m2s[cc] - 2.f * mm + m2s[dd], 0.f);
            const float pdist = (pd2 > 0.f) ? sqrtf(pd2) : 0.f;
            const float h = fmaxf(2.f * DELTA_DIST - pdist, 0.f);
            hs = h * h;
        }
    }
    // block reduce hs
    const int lane = tid & 31, wid = tid >> 5;   // 18 warps
#pragma unroll
    for (int off = 16; off; off >>= 1) hs += __shfl_down_sync(0xffffffffu, hs, off);
    if (lane == 0) red[wid] = hs;
    __syncthreads();
    float hs_tot = 0.f;
    if (tid < 32) {
        float v = (tid < 18) ? red[tid] : 0.f;
#pragma unroll
        for (int off = 16; off; off >>= 1) v += __shfl_down_sync(0xffffffffu, v, off);
        hs_tot = v;
    }
    __syncthreads();
    // block reduce regp
#pragma unroll
    for (int off = 16; off; off >>= 1) regp += __shfl_down_sync(0xffffffffu, regp, off);
    if (lane == 0) red[wid] = regp;
    __syncthreads();
    if (tid == 0) {
        float reg_tot = 0.f;
        for (int i = 0; i < 18; i++) reg_tot += red[i];
        const float dist_per = hs_tot / (2.f * ncf * (ncf - 1.f) + EPSV);
        if (nc > 1) atomicAdd(&g_distreg[0], dist_per / (float)B);
        if (nc > 0) atomicAdd(&g_distreg[1], reg_tot / ncf / (float)B);
    }
}

// ---------------------------------------------------------------------------
// K3: variance term. Per pixel: distance to its own cluster mean (one-hot t).
// grid (144, 8), 256 threads, 4 pixels/thread.
// ---------------------------------------------------------------------------
__global__ __launch_bounds__(256) void k_var(const float* __restrict__ x) {
    __shared__ float ms[F * K];
    __shared__ float m2s[K];
    __shared__ float cvar_s[K];

    const int b   = blockIdx.y;
    const int tid = threadIdx.x;
    // F*K = 384 > 256 threads: strided load (round-2 bug: only 256 loaded)
    for (int i = tid; i < F * K; i += 256) ms[i] = g_means[b * F * K + i];
    if (tid < K) { m2s[tid] = g_m2[b * K + tid]; cvar_s[tid] = 0.f; }
    __syncthreads();

    const int l = blockIdx.x * 1024 + tid * 4;
    const uint32_t lab4 = *(const uint32_t*)(g_labels + (size_t)b * L + l);
    const int lab[4] = { (int)(lab4 & 255), (int)((lab4 >> 8) & 255),
                         (int)((lab4 >> 16) & 255), (int)((lab4 >> 24) & 255) };
    float x2[4] = {0.f, 0.f, 0.f, 0.f};
    float xm[4] = {0.f, 0.f, 0.f, 0.f};
    const float* xb = x + (size_t)(b * F) * L + l;
#pragma unroll
    for (int f = 0; f < F; f++) {
        const float4 v = __ldg((const float4*)(xb + (size_t)f * L));
        x2[0] += v.x * v.x;  xm[0] += v.x * ms[f * K + lab[0]];
        x2[1] += v.y * v.y;  xm[1] += v.y * ms[f * K + lab[1]];
        x2[2] += v.z * v.z;  xm[2] += v.z * ms[f * K + lab[2]];
        x2[3] += v.w * v.w;  xm[3] += v.w * ms[f * K + lab[3]];
    }
#pragma unroll
    for (int j = 0; j < 4; j++) {
        float d2 = fmaxf(x2[j] - 2.f * xm[j] + m2s[lab[j]], 0.f);
        const float dist = (d2 > 0.f) ? sqrtf(d2) : 0.f;
        const float h = dist - DELTA_VAR;
        if (h > 0.f) atomicAdd(&cvar_s[lab[j]], h * h);
    }
    __syncthreads();
    if (tid < K) atomicAdd(&g_cvar[b * K + tid], cvar_s[tid]);
}

// ---------------------------------------------------------------------------
// K4: finalize the scalar.
// ---------------------------------------------------------------------------
__global__ void k_final(const int* __restrict__ n_clusters, float* __restrict__ out) {
    __shared__ float tmp[B * K];
    __shared__ float vb[B];
    const int tid = threadIdx.x;
    if (tid < B * K) {
        const int b = tid / K, c = tid % K;
        const int nc = n_clusters[b];
        const float cv = g_cvar[tid] / (g_tsum[tid] + EPSV);
        tmp[tid] = (c < nc) ? cv : 0.f;
    }
    __syncthreads();
    if (tid < B) {
        const int nc = n_clusters[tid];
        float s = 0.f;
#pragma unroll
        for (int c = 0; c < K; c++) s += tmp[tid * K + c];
        const float vp = s / ((float)nc + EPSV);
        vb[tid] = (nc > 0) ? vp : 0.f;
    }
    __syncthreads();
    if (tid == 0) {
        float var_term = 0.f;
#pragma unroll
        for (int b2 = 0; b2 < B; b2++) var_term += vb[b2];
        var_term /= (float)B;
        out[0] = var_term + g_distreg[0] + GAMMA * g_distreg[1];
    }
}

// ---------------------------------------------------------------------------
extern "C" void kernel_launch(void* const* d_in, const int* in_sizes, int n_in,
                              void* d_out, int out_size) {
    const float* x  = (const float*)d_in[0];
    const float* t  = (const float*)d_in[1];
    const int*   nc = (const int*)d_in[2];
    float* out = (float*)d_out;

    k_init<<<12, 256>>>();
    dim3 g1(NCHUNK, B);
    k_sums<<<g1, 256>>>(x, t);
    k_means<<<B, 576>>>(nc);
    k_var<<<dim3(NCHUNK, B), 256>>>(x);
    k_final<<<1, 256>>>(nc, out);
}